// round 11
// baseline (speedup 1.0000x reference)
#include <cuda_runtime.h>
#include <cuda_bf16.h>
#include <cstdint>

// Problem constants
#define B_    128
#define T_    512
#define I_    512
#define H_    2048
#define O_    512
#define STEPS 510
#define K_    (H_ + I_)        // 2560 concatenated K ([h | x_t] vs [W_hh | W_ih])
#define KSPLIT 8
#define KCHUNK (K_ / KSPLIT)   // 320
#define KB     32              // k-width per smem stage
#define NSTAGE (KCHUNK / KB)   // 10
#define LDSS   40              // bf16 elements per smem row (20 words -> conflict-free)

#define SMEM_PER_BUF 20480     // bf16 elems: Ahi(5120) Alo(5120) Bhi(5120) Blo(5120)
#define SMEM_BYTES   (2 * SMEM_PER_BUF * 2)   // 81920 bytes, double buffered

#define NCTA 128

// -------- device scratch (static allocation only; no cudaMalloc allowed) ----
__device__ __nv_bfloat16 g_Whi[(size_t)H_ * K_];   // 10.5 MB
__device__ __nv_bfloat16 g_Wlo[(size_t)H_ * K_];   // 10.5 MB
__device__ float g_h[B_ * H_];                     // current hidden state (fp32)
__device__ float g_hsave[B_ * H_];                 // h at t == pad[b]
__device__ float g_bias[H_];                       // b_ih + b_hh
__device__ int   g_pad[B_];
__device__ float g_P[KSPLIT * B_ * H_];            // K-split fp32 partials (8 MB)
__device__ unsigned g_arrive[NCTA];                // distributed barrier flags

// ---------------------------------------------------------------------------
// Setup: pad extraction, h init, bias combine, W -> bf16 hi/lo split, bar reset
// ---------------------------------------------------------------------------
__global__ void setup_kernel(const float* __restrict__ x,
                             const float* __restrict__ h0,
                             const float* __restrict__ Wih,
                             const float* __restrict__ bih,
                             const float* __restrict__ Whh,
                             const float* __restrict__ bhh) {
    long long idx    = (long long)blockIdx.x * blockDim.x + threadIdx.x;
    long long stride = (long long)gridDim.x * blockDim.x;

    // barrier flags must be reset on every replay
    for (long long i = idx; i < NCTA; i += stride) g_arrive[i] = 0u;

    // logical W[n][k] = (k < H) ? W_hh[n][k] : W_ih[n][k-H]
    for (long long i = idx; i < (long long)H_ * K_; i += stride) {
        int n = (int)(i / K_);
        int k = (int)(i % K_);
        float w = (k < H_) ? Whh[(size_t)n * H_ + k] : Wih[(size_t)n * I_ + (k - H_)];
        __nv_bfloat16 hi = __float2bfloat16(w);
        float lo = w - __bfloat162float(hi);
        g_Whi[i] = hi;
        g_Wlo[i] = __float2bfloat16(lo);
    }
    for (long long i = idx; i < (long long)B_ * H_; i += stride)
        g_h[i] = h0[i % H_];
    for (long long i = idx; i < H_; i += stride)
        g_bias[i] = bih[i] + bhh[i];
    for (long long i = idx; i < B_; i += stride)
        g_pad[i] = (int)(x[i * (long long)(T_ * I_) + (long long)(T_ - 1) * I_] + 0.5f);
}

// ---------------------------------------------------------------------------
// bf16 MMA: D += A * B  (m16n8k16, fp32 accumulate)
// ---------------------------------------------------------------------------
__device__ __forceinline__ void mma_bf16(float c[4], const uint32_t a[4],
                                         uint32_t b0, uint32_t b1) {
    asm volatile(
        "mma.sync.aligned.m16n8k16.row.col.f32.bf16.bf16.f32 "
        "{%0,%1,%2,%3}, {%4,%5,%6,%7}, {%8,%9}, {%0,%1,%2,%3};"
        : "+f"(c[0]), "+f"(c[1]), "+f"(c[2]), "+f"(c[3])
        : "r"(a[0]), "r"(a[1]), "r"(a[2]), "r"(a[3]), "r"(b0), "r"(b1));
}

// Distributed grid barrier across the 128 co-resident CTAs.
// Arrival: per-thread gpu fence, CTA sync, then CTA's own flag slot gets a
// release-store of the epoch (no contention). Detection: threads 0..127 each
// acquire-poll one distinct slot. Epochs are monotonic within a replay;
// setup_kernel zeroes the slots between replays.
__device__ __forceinline__ void grid_barrier(int bx, unsigned epoch) {
    __threadfence();            // make this thread's global stores visible gpu-wide
    __syncthreads();            // all threads of the CTA have fenced
    if (threadIdx.x == 0) {
        asm volatile("st.release.gpu.u32 [%0], %1;"
                     :: "l"(&g_arrive[bx]), "r"(epoch) : "memory");
    }
    if (threadIdx.x < NCTA) {
        unsigned v;
        do {
            asm volatile("ld.acquire.gpu.u32 %0, [%1];"
                         : "=r"(v) : "l"(&g_arrive[threadIdx.x]) : "memory");
        } while (v < epoch);
    }
    __syncthreads();
}

// ---------------------------------------------------------------------------
// Persistent RNN kernel: all 510 steps in one launch. Grid = 128 CTAs (all
// co-resident, <= SM count) x 256 threads. CTA (ks = bx&7, ni = bx>>3)
// computes the K-chunk [ks*320,+320) partial of pre-activation tile
// [:, ni*128:+128) with bf16x3 split-product MMAs, writes fp32 partials,
// grid-syncs, then each CTA reduces+biases+tanh's one batch row and
// snapshots h where t == pad[b], grid-syncs again.
// ---------------------------------------------------------------------------
__global__ void __launch_bounds__(256, 1)
rnn_persistent(const float* __restrict__ x) {
    extern __shared__ __nv_bfloat16 smem[];

    const int bx   = blockIdx.x;
    const int ks   = bx & 7;
    const int ni   = bx >> 3;
    const int tid  = threadIdx.x;
    const int wid  = tid >> 5;
    const int lane = tid & 31;
    const int wm   = wid & 3;      // warp m-tile: rows wm*32 .. +32
    const int wn   = wid >> 2;     // warp n-tile: cols wn*64 .. +64
    const int g    = lane >> 2;
    const int tig  = lane & 3;

    const int k0    = ks * KCHUNK;
    const int nbase = ni * 128;

    // loader mappings
    const int a_row = tid >> 3;          // A: 32 rows x 32 k per pass, 4 passes
    const int a_kq  = (tid & 7) * 4;
    const int b_n   = tid >> 1;          // B: 128 rows, 16 bf16 each
    const int b_kq  = (tid & 1) * 16;

    float c[2][8][4];
    float4 av[4];
    uint4  bv[4];

    for (int t = 0; t < STEPS; t++) {
        #pragma unroll
        for (int mt = 0; mt < 2; mt++)
            #pragma unroll
            for (int nt = 0; nt < 8; nt++)
                #pragma unroll
                for (int j = 0; j < 4; j++) c[mt][nt][j] = 0.0f;

        // ---------------- GEMM over NSTAGE double-buffered k-stages --------
        // Pipeline: stage s registers -> smem, issue global loads for s+1,
        // compute stage s. One __syncthreads before store, one after compute.
        {
            // prologue: global loads for stage 0
            {
                const int kg = k0;
                const int gk = kg + a_kq;
                #pragma unroll
                for (int rr = 0; rr < 4; rr++) {
                    const int m = a_row + rr * 32;
                    if (gk < H_)
                        av[rr] = __ldcg(reinterpret_cast<const float4*>(&g_h[m * H_ + gk]));
                    else
                        av[rr] = *reinterpret_cast<const float4*>(
                            &x[(size_t)m * (T_ * I_) + (size_t)t * I_ + (gk - H_)]);
                }
                const size_t base = (size_t)(nbase + b_n) * K_ + (kg + b_kq);
                bv[0] = *reinterpret_cast<const uint4*>(&g_Whi[base]);
                bv[1] = *reinterpret_cast<const uint4*>(&g_Whi[base + 8]);
                bv[2] = *reinterpret_cast<const uint4*>(&g_Wlo[base]);
                bv[3] = *reinterpret_cast<const uint4*>(&g_Wlo[base + 8]);
            }

            #pragma unroll 2
            for (int s = 0; s < NSTAGE; s++) {
                // store staged registers into buffer (s&1)
                {
                    __nv_bfloat16* sA_hi = smem + (s & 1) * SMEM_PER_BUF;
                    __nv_bfloat16* sA_lo = sA_hi + 5120;
                    __nv_bfloat16* sB_hi = sA_hi + 10240;
                    __nv_bfloat16* sB_lo = sA_hi + 15360;
                    #pragma unroll
                    for (int rr = 0; rr < 4; rr++) {
                        const int m = a_row + rr * 32;
                        float vv[4] = {av[rr].x, av[rr].y, av[rr].z, av[rr].w};
                        #pragma unroll
                        for (int j = 0; j < 4; j += 2) {
                            __nv_bfloat16 h0b = __float2bfloat16(vv[j]);
                            __nv_bfloat16 h1b = __float2bfloat16(vv[j + 1]);
                            __nv_bfloat162 hp; hp.x = h0b; hp.y = h1b;
                            __nv_bfloat162 lp;
                            lp.x = __float2bfloat16(vv[j]     - __bfloat162float(h0b));
                            lp.y = __float2bfloat16(vv[j + 1] - __bfloat162float(h1b));
                            *reinterpret_cast<uint32_t*>(&sA_hi[m * LDSS + a_kq + j]) =
                                *reinterpret_cast<uint32_t*>(&hp);
                            *reinterpret_cast<uint32_t*>(&sA_lo[m * LDSS + a_kq + j]) =
                                *reinterpret_cast<uint32_t*>(&lp);
                        }
                    }
                    *reinterpret_cast<uint4*>(&sB_hi[b_n * LDSS + b_kq])     = bv[0];
                    *reinterpret_cast<uint4*>(&sB_hi[b_n * LDSS + b_kq + 8]) = bv[1];
                    *reinterpret_cast<uint4*>(&sB_lo[b_n * LDSS + b_kq])     = bv[2];
                    *reinterpret_cast<uint4*>(&sB_lo[b_n * LDSS + b_kq + 8]) = bv[3];
                }
                __syncthreads();

                // issue global loads for stage s+1 (latency hidden by compute)
                if (s + 1 < NSTAGE) {
                    const int kg = k0 + (s + 1) * KB;
                    const int gk = kg + a_kq;
                    #pragma unroll
                    for (int rr = 0; rr < 4; rr++) {
                        const int m = a_row + rr * 32;
                        if (gk < H_)
                            av[rr] = __ldcg(reinterpret_cast<const float4*>(&g_h[m * H_ + gk]));
                        else
                            av[rr] = *reinterpret_cast<const float4*>(
                                &x[(size_t)m * (T_ * I_) + (size_t)t * I_ + (gk - H_)]);
                    }
                    const size_t base = (size_t)(nbase + b_n) * K_ + (kg + b_kq);
                    bv[0] = *reinterpret_cast<const uint4*>(&g_Whi[base]);
                    bv[1] = *reinterpret_cast<const uint4*>(&g_Whi[base + 8]);
                    bv[2] = *reinterpret_cast<const uint4*>(&g_Wlo[base]);
                    bv[3] = *reinterpret_cast<const uint4*>(&g_Wlo[base + 8]);
                }

                // compute stage s from buffer (s&1)
                {
                    const __nv_bfloat16* sA_hi = smem + (s & 1) * SMEM_PER_BUF;
                    const __nv_bfloat16* sA_lo = sA_hi + 5120;
                    const __nv_bfloat16* sB_hi = sA_hi + 10240;
                    const __nv_bfloat16* sB_lo = sA_hi + 15360;
                    #pragma unroll
                    for (int k2 = 0; k2 < 2; k2++) {
                        const int kk = k2 * 16 + tig * 2;
                        uint32_t ahi[2][4], alo[2][4];
                        #pragma unroll
                        for (int mt = 0; mt < 2; mt++) {
                            const int m = wm * 32 + mt * 16 + g;
                            ahi[mt][0] = *reinterpret_cast<const uint32_t*>(&sA_hi[m * LDSS + kk]);
                            ahi[mt][1] = *reinterpret_cast<const uint32_t*>(&sA_hi[(m + 8) * LDSS + kk]);
                            ahi[mt][2] = *reinterpret_cast<const uint32_t*>(&sA_hi[m * LDSS + kk + 8]);
                            ahi[mt][3] = *reinterpret_cast<const uint32_t*>(&sA_hi[(m + 8) * LDSS + kk + 8]);
                            alo[mt][0] = *reinterpret_cast<const uint32_t*>(&sA_lo[m * LDSS + kk]);
                            alo[mt][1] = *reinterpret_cast<const uint32_t*>(&sA_lo[(m + 8) * LDSS + kk]);
                            alo[mt][2] = *reinterpret_cast<const uint32_t*>(&sA_lo[m * LDSS + kk + 8]);
                            alo[mt][3] = *reinterpret_cast<const uint32_t*>(&sA_lo[(m + 8) * LDSS + kk + 8]);
                        }
                        #pragma unroll
                        for (int nt = 0; nt < 8; nt++) {
                            const int n = wn * 64 + nt * 8 + g;
                            const uint32_t bhi0 = *reinterpret_cast<const uint32_t*>(&sB_hi[n * LDSS + kk]);
                            const uint32_t bhi1 = *reinterpret_cast<const uint32_t*>(&sB_hi[n * LDSS + kk + 8]);
                            const uint32_t blo0 = *reinterpret_cast<const uint32_t*>(&sB_lo[n * LDSS + kk]);
                            const uint32_t blo1 = *reinterpret_cast<const uint32_t*>(&sB_lo[n * LDSS + kk + 8]);
                            #pragma unroll
                            for (int mt = 0; mt < 2; mt++) {
                                mma_bf16(c[mt][nt], ahi[mt], bhi0, bhi1);  // hi*hi
                                mma_bf16(c[mt][nt], ahi[mt], blo0, blo1);  // hi*lo
                                mma_bf16(c[mt][nt], alo[mt], bhi0, bhi1);  // lo*hi
                            }
                        }
                    }
                }
                __syncthreads();
            }
        }

        // ---------------- write fp32 partials ------------------------------
        #pragma unroll
        for (int mt = 0; mt < 2; mt++) {
            #pragma unroll
            for (int nt = 0; nt < 8; nt++) {
                const int m = wm * 32 + mt * 16 + g;
                const int n = nbase + wn * 64 + nt * 8 + tig * 2;
                float2 v0 = make_float2(c[mt][nt][0], c[mt][nt][1]);
                float2 v1 = make_float2(c[mt][nt][2], c[mt][nt][3]);
                *reinterpret_cast<float2*>(&g_P[(size_t)(ks * B_ + m) * H_ + n])     = v0;
                *reinterpret_cast<float2*>(&g_P[(size_t)(ks * B_ + m + 8) * H_ + n]) = v1;
            }
        }

        grid_barrier(bx, 2u * (unsigned)t + 1u);

        // ---------------- reduce + bias + tanh; CTA bx owns batch row bx ---
        {
            const int m = bx;
            const int n = tid * 8;
            float4 s0 = *reinterpret_cast<const float4*>(&g_bias[n]);
            float4 s1 = *reinterpret_cast<const float4*>(&g_bias[n + 4]);
            #pragma unroll
            for (int p = 0; p < KSPLIT; p++) {
                const float4 v0 = __ldcg(reinterpret_cast<const float4*>(
                    &g_P[(size_t)(p * B_ + m) * H_ + n]));
                const float4 v1 = __ldcg(reinterpret_cast<const float4*>(
                    &g_P[(size_t)(p * B_ + m) * H_ + n + 4]));
                s0.x += v0.x; s0.y += v0.y; s0.z += v0.z; s0.w += v0.w;
                s1.x += v1.x; s1.y += v1.y; s1.z += v1.z; s1.w += v1.w;
            }
            float4 h0v, h1v;
            h0v.x = tanhf(s0.x); h0v.y = tanhf(s0.y); h0v.z = tanhf(s0.z); h0v.w = tanhf(s0.w);
            h1v.x = tanhf(s1.x); h1v.y = tanhf(s1.y); h1v.z = tanhf(s1.z); h1v.w = tanhf(s1.w);
            *reinterpret_cast<float4*>(&g_h[m * H_ + n])     = h0v;
            *reinterpret_cast<float4*>(&g_h[m * H_ + n + 4]) = h1v;
            if (g_pad[m] == t) {
                *reinterpret_cast<float4*>(&g_hsave[m * H_ + n])     = h0v;
                *reinterpret_cast<float4*>(&g_hsave[m * H_ + n + 4]) = h1v;
            }
        }

        grid_barrier(bx, 2u * (unsigned)t + 2u);
    }
}

// ---------------------------------------------------------------------------
// Final FC: out[b][o] = b_fc[o] + hsave[b] . W_fc[o]
// Grid: 64 b-pairs x 4 o-quarters = 256 blocks, 128 threads.
// ---------------------------------------------------------------------------
__global__ void __launch_bounds__(128)
fc_kernel(const float* __restrict__ Wfc, const float* __restrict__ bfc,
          float* __restrict__ out) {
    __shared__ float hs[2 * H_];
    const int bb  = blockIdx.x >> 2;
    const int oq  = blockIdx.x & 3;
    const int tid = threadIdx.x;

    const float* src = &g_hsave[(size_t)(bb * 2) * H_];
    for (int i = tid * 4; i < 2 * H_; i += 128 * 4)
        *reinterpret_cast<float4*>(&hs[i]) =
            *reinterpret_cast<const float4*>(&src[i]);
    __syncthreads();

    const int o = oq * 128 + tid;
    const float* w = &Wfc[(size_t)o * H_];
    float a0 = 0.0f, a1 = 0.0f;
    for (int n = 0; n < H_; n += 4) {
        const float4 wv  = *reinterpret_cast<const float4*>(&w[n]);
        const float4 h0v = *reinterpret_cast<const float4*>(&hs[n]);
        const float4 h1v = *reinterpret_cast<const float4*>(&hs[H_ + n]);
        a0 += wv.x * h0v.x + wv.y * h0v.y + wv.z * h0v.z + wv.w * h0v.w;
        a1 += wv.x * h1v.x + wv.y * h1v.y + wv.z * h1v.z + wv.w * h1v.w;
    }
    const float bias = bfc[o];
    out[(size_t)(bb * 2 + 0) * O_ + o] = a0 + bias;
    out[(size_t)(bb * 2 + 1) * O_ + o] = a1 + bias;
}

// ---------------------------------------------------------------------------
extern "C" void kernel_launch(void* const* d_in, const int* in_sizes, int n_in,
                              void* d_out, int out_size) {
    (void)in_sizes; (void)n_in; (void)out_size;
    const float* x   = (const float*)d_in[0];
    const float* h0  = (const float*)d_in[1];
    const float* Wih = (const float*)d_in[2];
    const float* bih = (const float*)d_in[3];
    const float* Whh = (const float*)d_in[4];
    const float* bhh = (const float*)d_in[5];
    const float* Wfc = (const float*)d_in[6];
    const float* bfc = (const float*)d_in[7];
    float* out = (float*)d_out;

    // idempotent, capture-safe, no static guards (harness rule)
    cudaFuncSetAttribute(rnn_persistent,
                         cudaFuncAttributeMaxDynamicSharedMemorySize, SMEM_BYTES);

    setup_kernel<<<2048, 256>>>(x, h0, Wih, bih, Whh, bhh);
    rnn_persistent<<<NCTA, 256, SMEM_BYTES>>>(x);
    fc_kernel<<<256, 128>>>(Wfc, bfc, out);
}

// round 14
// speedup vs baseline: 1.1777x; 1.1777x over previous
#include <cuda_runtime.h>
#include <cuda_bf16.h>
#include <cstdint>

// Problem constants
#define B_    128
#define T_    512
#define I_    512
#define H_    2048
#define O_    512
#define STEPS 510
#define K_    (H_ + I_)        // 2560 concatenated K ([h | x_t] vs [W_hh | W_ih])
#define KSPLIT 8
#define KCHUNK 320             // K per CTA
#define NCTA   128

// ---- arch-feature gate: tcgen05 exists only on sm_103a-targeted passes ----
#if defined(__CUDA_ARCH__) && defined(__CUDA_ARCH_FEAT_SM103_ALL)
#define TC_PATH 1
#else
#define TC_PATH 0
#endif

// ---- tcgen05-path constants ----
#define KB_TC     64           // bf16 k per smem stage (one SW128 atom row)
#define NSTAGE_TC 5            // 320 / 64
#define SM_TMEM   0
#define SM_MBAR   8
#define SM_BUF    1024         // 1024-aligned for SW128 descriptors
#define MAT_BYTES 16384        // 128 rows x 128 bytes
#define BUF_BYTES (4 * MAT_BYTES)   // Ahi, Alo, Bhi, Blo (single buffer)
// idesc kind::f16: f32 acc(1<<4), bf16 A(1<<7), bf16 B(1<<10), N=128(16<<17), M=128(8<<24)
#define IDESC 0x8200490u

// ---- HMMA-fallback constants ----
#define KB_HM     32
#define NSTAGE_HM 10           // 320 / 32
#define LDSS      40           // bf16 per smem row (conflict-free)
#define HM_PER_BUF 20480       // bf16 elems: Ahi Alo Bhi Blo (5120 each)

// dynamic smem: max of both paths (HMMA: 81920, TC: 1024+65536=66560)
#define SMEM_TOTAL 81920

// -------- device scratch (static allocation only) ---------------------------
// Layout of g_Whi/g_Wlo depends on compiled path (setup writes the matching one):
//   TC_PATH:  per-(ni,ks,stage) 16KB SW128 smem-image blocks
//   fallback: linear [n][k]
__device__ __nv_bfloat16 g_Whi[(size_t)H_ * K_];   // 10.5 MB
__device__ __nv_bfloat16 g_Wlo[(size_t)H_ * K_];   // 10.5 MB
__device__ float g_h[B_ * H_];
__device__ float g_hsave[B_ * H_];
__device__ float g_bias[H_];
__device__ int   g_pad[B_];
__device__ float g_P[KSPLIT * B_ * H_];            // fp32 K-split partials (8 MB)
__device__ unsigned g_arrive[NCTA];                // distributed barrier flags

// ---------------------------------------------------------------------------
// Setup: barrier reset, pad, h init, bias, W -> bf16 hi/lo split.
// ---------------------------------------------------------------------------
__global__ void setup_kernel(const float* __restrict__ x,
                             const float* __restrict__ h0,
                             const float* __restrict__ Wih,
                             const float* __restrict__ bih,
                             const float* __restrict__ Whh,
                             const float* __restrict__ bhh) {
    long long idx    = (long long)blockIdx.x * blockDim.x + threadIdx.x;
    long long stride = (long long)gridDim.x * blockDim.x;

    for (long long i = idx; i < NCTA; i += stride) g_arrive[i] = 0u;

    for (long long i = idx; i < (long long)H_ * K_; i += stride) {
        int n = (int)(i / K_);
        int k = (int)(i % K_);
        float w = (k < H_) ? Whh[(size_t)n * H_ + k] : Wih[(size_t)n * I_ + (k - H_)];
        __nv_bfloat16 hi = __float2bfloat16(w);
        float lof = w - __bfloat162float(hi);
#if TC_PATH
        // swizzled block layout for SS-mode descriptors
        int ni = n >> 7, np = n & 127;
        int ks = k / KCHUNK, r = k % KCHUNK, s = r >> 6, kk = r & 63;
        size_t blk = (size_t)((ni * 8 + ks) * NSTAGE_TC + s);
        uint32_t off = (uint32_t)(np * 128 + kk * 2);
        uint32_t sw  = off ^ ((off >> 3) & 0x70);
        size_t di = blk * 8192 + (sw >> 1);
#else
        size_t di = (size_t)i;   // linear
#endif
        g_Whi[di] = hi;
        g_Wlo[di] = __float2bfloat16(lof);
    }
    for (long long i = idx; i < (long long)B_ * H_; i += stride)
        g_h[i] = h0[i % H_];
    for (long long i = idx; i < H_; i += stride)
        g_bias[i] = bih[i] + bhh[i];
    for (long long i = idx; i < B_; i += stride)
        g_pad[i] = (int)(x[i * (long long)(T_ * I_) + (long long)(T_ - 1) * I_] + 0.5f);
}

// ---------------------------------------------------------------------------
// helpers
// ---------------------------------------------------------------------------
__device__ __forceinline__ void split2(float a, float b, uint32_t& hi, uint32_t& lo) {
    __nv_bfloat162 h, l;
    h.x = __float2bfloat16(a); h.y = __float2bfloat16(b);
    l.x = __float2bfloat16(a - __bfloat162float(h.x));
    l.y = __float2bfloat16(b - __bfloat162float(h.y));
    hi = *reinterpret_cast<uint32_t*>(&h);
    lo = *reinterpret_cast<uint32_t*>(&l);
}

// Distributed grid barrier across the 128 co-resident CTAs.
__device__ __forceinline__ void grid_barrier(int bx, unsigned epoch) {
    __threadfence();
    __syncthreads();
    if (threadIdx.x == 0) {
        asm volatile("st.release.gpu.u32 [%0], %1;"
                     :: "l"(&g_arrive[bx]), "r"(epoch) : "memory");
    }
    if (threadIdx.x < NCTA) {
        unsigned v;
        do {
            asm volatile("ld.acquire.gpu.u32 %0, [%1];"
                         : "=r"(v) : "l"(&g_arrive[threadIdx.x]) : "memory");
        } while (v < epoch);
    }
    __syncthreads();
}

#if TC_PATH
__device__ __forceinline__ uint32_t elect_one() {
    uint32_t p;
    asm volatile("{\n\t.reg .pred p;\n\telect.sync _|p, 0xFFFFFFFF;\n\t"
                 "selp.b32 %0, 1, 0, p;\n\t}" : "=r"(p));
    return p;
}
__device__ __forceinline__ uint64_t sdesc(uint32_t addr) {
    // SW128 K-major: layout=2, version=1, SBO=64, LBO=1
    const uint64_t base = (2ULL << 61) | (1ULL << 46) | (64ULL << 32) | (1ULL << 16);
    return base | ((addr >> 4) & 0x3FFF);
}
__device__ __forceinline__ void mma_ss(uint32_t d, uint64_t ad, uint64_t bd,
                                       uint32_t idesc, uint32_t enable) {
    asm volatile(
        "{\n\t.reg .pred p;\n\tsetp.ne.u32 p, %4, 0;\n\t"
        "tcgen05.mma.cta_group::1.kind::f16 [%0], %1, %2, %3, {%5,%5,%5,%5}, p;\n\t}"
        :: "r"(d), "l"(ad), "l"(bd), "r"(idesc), "r"(enable), "r"(0u) : "memory");
}
__device__ __forceinline__ void mbar_wait(uint32_t addr, unsigned parity) {
    asm volatile(
        "{\n\t.reg .pred P1;\n\t"
        "WAIT_LOOP_%=:\n\t"
        "mbarrier.try_wait.parity.acquire.cta.shared::cta.b64 P1, [%0], %1, 0x989680;\n\t"
        "@P1 bra.uni WAIT_DONE_%=;\n\t"
        "bra.uni WAIT_LOOP_%=;\n\t"
        "WAIT_DONE_%=:\n\t}"
        :: "r"(addr), "r"(parity) : "memory");
}
#else
// bf16 MMA: D += A * B  (m16n8k16, fp32 accumulate) — fallback tensor path
__device__ __forceinline__ void mma_bf16(float c[4], const uint32_t a[4],
                                         uint32_t b0, uint32_t b1) {
    asm volatile(
        "mma.sync.aligned.m16n8k16.row.col.f32.bf16.bf16.f32 "
        "{%0,%1,%2,%3}, {%4,%5,%6,%7}, {%8,%9}, {%0,%1,%2,%3};"
        : "+f"(c[0]), "+f"(c[1]), "+f"(c[2]), "+f"(c[3])
        : "r"(a[0]), "r"(a[1]), "r"(a[2]), "r"(a[3]), "r"(b0), "r"(b1));
}
#endif

// ---------------------------------------------------------------------------
// Persistent RNN kernel: all 510 steps. 128 CTAs x 256 threads, 1 CTA/SM.
// CTA (ks=bx&7, ni=bx>>3): D[128 batch x 128 n] over K-chunk [ks*320,+320)
// with bf16x3 split products; writes fp32 partials; grid barrier; fused
// reduce+bias+tanh (CTA bx owns batch row bx) with pad snapshot; barrier.
// ---------------------------------------------------------------------------
__global__ void __launch_bounds__(256, 1) __cluster_dims__(1, 1, 1)
rnn_persistent(const float* __restrict__ x) {
    extern __shared__ char smemc[];

    const int bx   = blockIdx.x;
    const int ks   = bx & 7;
    const int ni   = bx >> 3;
    const int tid  = threadIdx.x;
    const int wid  = tid >> 5;
    const int lane = tid & 31;
    const int k0    = ks * KCHUNK;
    const int nbase = ni * 128;

#if TC_PATH
    // ===================== tcgen05 mainloop (conservative) =================
    uint32_t smem_u32;
    asm("{ .reg .u64 t; cvta.to.shared.u64 t, %1; cvt.u32.u64 %0, t; }"
        : "=r"(smem_u32) : "l"(smemc));

    const int mrow = tid >> 1;     // A-fill: thread -> (row, 32-float half)
    const int half = tid & 1;
    const int mx   = mrow & 7;     // swizzle XOR for row's 16B chunks

    // TMEM alloc by warp 0 only (test_mma.cu / test_mma_mxf8_512 pattern)
    if (wid == 0) {
        asm volatile("tcgen05.alloc.cta_group::1.sync.aligned.shared::cta.b32 [%0], %1;"
                     :: "r"(smem_u32 + SM_TMEM), "r"(512) : "memory");
    }
    if (tid == 0) {
        asm volatile("mbarrier.init.shared.b64 [%0], %1;"
                     :: "r"(smem_u32 + SM_MBAR), "r"(1) : "memory");
    }
    __syncthreads();
    uint32_t tmem;
    asm volatile("ld.shared.b32 %0, [%1];" : "=r"(tmem) : "r"(smem_u32 + SM_TMEM));

    const uint32_t mbar = smem_u32 + SM_MBAR;
    char* bufc = smemc + SM_BUF;           // single buffer
    const uint32_t ab = smem_u32 + SM_BUF;
    const uint64_t dAh = sdesc(ab);
    const uint64_t dAl = sdesc(ab + MAT_BYTES);
    const uint64_t dBh = sdesc(ab + 2 * MAT_BYTES);
    const uint64_t dBl = sdesc(ab + 3 * MAT_BYTES);

    unsigned epoch = 0;   // one commit per stage; exactly one outstanding

    for (int t = 0; t < STEPS; t++) {
        for (int s = 0; s < NSTAGE_TC; s++) {
            const int kg = k0 + s * KB_TC;

            // ---- A fill: 128 x 64 fp32 -> bf16 hi/lo, SW128-swizzled ----
            {
                const float* srcA = (kg < H_)
                    ? &g_h[mrow * H_ + kg + half * 32]
                    : &x[(size_t)mrow * (T_ * I_) + (size_t)t * I_ + (kg - H_) + half * 32];
                char* bh = bufc + mrow * 128;
                char* bl = bh + MAT_BYTES;
                #pragma unroll
                for (int i2 = 0; i2 < 4; i2++) {
                    float4 f0 = __ldcg(reinterpret_cast<const float4*>(srcA + i2 * 8));
                    float4 f1 = __ldcg(reinterpret_cast<const float4*>(srcA + i2 * 8 + 4));
                    uint4 hv, lv;
                    split2(f0.x, f0.y, hv.x, lv.x);
                    split2(f0.z, f0.w, hv.y, lv.y);
                    split2(f1.x, f1.y, hv.z, lv.z);
                    split2(f1.z, f1.w, hv.w, lv.w);
                    const int q = ((half * 4 + i2) ^ mx) * 16;
                    *reinterpret_cast<uint4*>(bh + q) = hv;
                    *reinterpret_cast<uint4*>(bl + q) = lv;
                }
            }
            // ---- B fill: pre-swizzled 16KB blocks, pure copy ----
            {
                const size_t blk = (size_t)((ni * 8 + ks) * NSTAGE_TC + s);
                const uint4* sh = reinterpret_cast<const uint4*>(g_Whi) + blk * 1024;
                const uint4* sl = reinterpret_cast<const uint4*>(g_Wlo) + blk * 1024;
                uint4* dh = reinterpret_cast<uint4*>(bufc + 2 * MAT_BYTES);
                uint4* dl = reinterpret_cast<uint4*>(bufc + 3 * MAT_BYTES);
                #pragma unroll
                for (int i2 = 0; i2 < 4; i2++) {
                    dh[i2 * 256 + tid] = sh[i2 * 256 + tid];
                    dl[i2 * 256 + tid] = sl[i2 * 256 + tid];
                }
            }
            asm volatile("fence.proxy.async.shared::cta;" ::: "memory");
            __syncthreads();

            // ---- MMA issue: 4 k16-steps x 3 split products, then commit ----
            if (wid == 0) {
                asm volatile("tcgen05.fence::after_thread_sync;" ::: "memory");
                if (elect_one()) {
                    #pragma unroll
                    for (int j = 0; j < 4; j++) {
                        const unsigned en0 = (s == 0 && j == 0) ? 0u : 1u;
                        mma_ss(tmem, dAh + 2 * j, dBh + 2 * j, IDESC, en0);  // hi*hi
                        mma_ss(tmem, dAh + 2 * j, dBl + 2 * j, IDESC, 1u);  // hi*lo
                        mma_ss(tmem, dAl + 2 * j, dBh + 2 * j, IDESC, 1u);  // lo*hi
                    }
                    asm volatile(
                        "tcgen05.commit.cta_group::1.mbarrier::arrive::one.shared::cluster.b64 [%0];"
                        :: "r"(mbar) : "memory");
                }
            }
            // all threads wait for this stage's MMAs (buffer reusable after)
            mbar_wait(mbar, epoch & 1);
            epoch++;
            __syncthreads();
        }

        asm volatile("tcgen05.fence::after_thread_sync;" ::: "memory");

        // ---- epilogue: warps 0-3 read D from TMEM, write fp32 partials ----
        if (wid < 4) {
            const int mr = wid * 32 + lane;
            float* dst = &g_P[(size_t)(ks * B_ + mr) * H_ + nbase];
            #pragma unroll
            for (int cb = 0; cb < 4; cb++) {
                uint32_t r[32];
                asm volatile(
                    "tcgen05.ld.sync.aligned.32x32b.x32.b32 "
                    "{%0, %1, %2, %3, %4, %5, %6, %7, "
                    " %8, %9, %10, %11, %12, %13, %14, %15, "
                    " %16, %17, %18, %19, %20, %21, %22, %23, "
                    " %24, %25, %26, %27, %28, %29, %30, %31}, [%32];"
                    : "=r"(r[0]), "=r"(r[1]), "=r"(r[2]), "=r"(r[3]),
                      "=r"(r[4]), "=r"(r[5]), "=r"(r[6]), "=r"(r[7]),
                      "=r"(r[8]), "=r"(r[9]), "=r"(r[10]), "=r"(r[11]),
                      "=r"(r[12]), "=r"(r[13]), "=r"(r[14]), "=r"(r[15]),
                      "=r"(r[16]), "=r"(r[17]), "=r"(r[18]), "=r"(r[19]),
                      "=r"(r[20]), "=r"(r[21]), "=r"(r[22]), "=r"(r[23]),
                      "=r"(r[24]), "=r"(r[25]), "=r"(r[26]), "=r"(r[27]),
                      "=r"(r[28]), "=r"(r[29]), "=r"(r[30]), "=r"(r[31])
                    : "r"(tmem + cb * 32));
                asm volatile("tcgen05.wait::ld.sync.aligned;" ::: "memory");
                #pragma unroll
                for (int i2 = 0; i2 < 8; i2++) {
                    float4 v = make_float4(__uint_as_float(r[i2 * 4 + 0]),
                                           __uint_as_float(r[i2 * 4 + 1]),
                                           __uint_as_float(r[i2 * 4 + 2]),
                                           __uint_as_float(r[i2 * 4 + 3]));
                    *reinterpret_cast<float4*>(dst + cb * 32 + i2 * 4) = v;
                }
            }
            asm volatile("tcgen05.fence::before_thread_sync;" ::: "memory");
        }

        grid_barrier(bx, 2u * (unsigned)t + 1u);

        // ---- reduce + bias + tanh; CTA bx owns batch row bx ----
        {
            const int m = bx;
            const int n = tid * 8;
            float4 s0 = *reinterpret_cast<const float4*>(&g_bias[n]);
            float4 s1 = *reinterpret_cast<const float4*>(&g_bias[n + 4]);
            #pragma unroll
            for (int p = 0; p < KSPLIT; p++) {
                const float4 v0 = __ldcg(reinterpret_cast<const float4*>(
                    &g_P[(size_t)(p * B_ + m) * H_ + n]));
                const float4 v1 = __ldcg(reinterpret_cast<const float4*>(
                    &g_P[(size_t)(p * B_ + m) * H_ + n + 4]));
                s0.x += v0.x; s0.y += v0.y; s0.z += v0.z; s0.w += v0.w;
                s1.x += v1.x; s1.y += v1.y; s1.z += v1.z; s1.w += v1.w;
            }
            float4 h0v, h1v;
            h0v.x = tanhf(s0.x); h0v.y = tanhf(s0.y); h0v.z = tanhf(s0.z); h0v.w = tanhf(s0.w);
            h1v.x = tanhf(s1.x); h1v.y = tanhf(s1.y); h1v.z = tanhf(s1.z); h1v.w = tanhf(s1.w);
            *reinterpret_cast<float4*>(&g_h[m * H_ + n])     = h0v;
            *reinterpret_cast<float4*>(&g_h[m * H_ + n + 4]) = h1v;
            if (g_pad[m] == t) {
                *reinterpret_cast<float4*>(&g_hsave[m * H_ + n])     = h0v;
                *reinterpret_cast<float4*>(&g_hsave[m * H_ + n + 4]) = h1v;
            }
        }

        grid_barrier(bx, 2u * (unsigned)t + 2u);
    }

    __syncthreads();
    if (tid == 0) {
        asm volatile("mbarrier.inval.shared.b64 [%0];" :: "r"(mbar) : "memory");
    }
    __syncthreads();
    if (wid == 0) {
        asm volatile("tcgen05.dealloc.cta_group::1.sync.aligned.b32 %0, %1;"
                     :: "r"(tmem), "r"(512));
    }

#else
    // ===================== HMMA fallback (R11-proven) ======================
    __nv_bfloat16* smem = reinterpret_cast<__nv_bfloat16*>(smemc);

    const int wm  = wid & 3;
    const int wn  = wid >> 2;
    const int g   = lane >> 2;
    const int tig = lane & 3;

    const int a_row = tid >> 3;
    const int a_kq  = (tid & 7) * 4;
    const int b_n   = tid >> 1;
    const int b_kq  = (tid & 1) * 16;

    float c[2][8][4];
    float4 av[4];
    uint4  bv[4];

    for (int t = 0; t < STEPS; t++) {
        #pragma unroll
        for (int mt = 0; mt < 2; mt++)
            #pragma unroll
            for (int nt = 0; nt < 8; nt++)
                #pragma unroll
                for (int j = 0; j < 4; j++) c[mt][nt][j] = 0.0f;

        {
            {
                const int kg = k0;
                const int gk = kg + a_kq;
                #pragma unroll
                for (int rr = 0; rr < 4; rr++) {
                    const int m = a_row + rr * 32;
                    if (gk < H_)
                        av[rr] = __ldcg(reinterpret_cast<const float4*>(&g_h[m * H_ + gk]));
                    else
                        av[rr] = *reinterpret_cast<const float4*>(
                            &x[(size_t)m * (T_ * I_) + (size_t)t * I_ + (gk - H_)]);
                }
                const size_t base = (size_t)(nbase + b_n) * K_ + (kg + b_kq);
                bv[0] = *reinterpret_cast<const uint4*>(&g_Whi[base]);
                bv[1] = *reinterpret_cast<const uint4*>(&g_Whi[base + 8]);
                bv[2] = *reinterpret_cast<const uint4*>(&g_Wlo[base]);
                bv[3] = *reinterpret_cast<const uint4*>(&g_Wlo[base + 8]);
            }

            #pragma unroll 2
            for (int s = 0; s < NSTAGE_HM; s++) {
                {
                    __nv_bfloat16* sA_hi = smem + (s & 1) * HM_PER_BUF;
                    __nv_bfloat16* sA_lo = sA_hi + 5120;
                    __nv_bfloat16* sB_hi = sA_hi + 10240;
                    __nv_bfloat16* sB_lo = sA_hi + 15360;
                    #pragma unroll
                    for (int rr = 0; rr < 4; rr++) {
                        const int m = a_row + rr * 32;
                        float vv[4] = {av[rr].x, av[rr].y, av[rr].z, av[rr].w};
                        #pragma unroll
                        for (int j = 0; j < 4; j += 2) {
                            uint32_t hp, lp;
                            split2(vv[j], vv[j + 1], hp, lp);
                            *reinterpret_cast<uint32_t*>(&sA_hi[m * LDSS + a_kq + j]) = hp;
                            *reinterpret_cast<uint32_t*>(&sA_lo[m * LDSS + a_kq + j]) = lp;
                        }
                    }
                    *reinterpret_cast<uint4*>(&sB_hi[b_n * LDSS + b_kq])     = bv[0];
                    *reinterpret_cast<uint4*>(&sB_hi[b_n * LDSS + b_kq + 8]) = bv[1];
                    *reinterpret_cast<uint4*>(&sB_lo[b_n * LDSS + b_kq])     = bv[2];
                    *reinterpret_cast<uint4*>(&sB_lo[b_n * LDSS + b_kq + 8]) = bv[3];
                }
                __syncthreads();

                if (s + 1 < NSTAGE_HM) {
                    const int kg = k0 + (s + 1) * KB_HM;
                    const int gk = kg + a_kq;
                    #pragma unroll
                    for (int rr = 0; rr < 4; rr++) {
                        const int m = a_row + rr * 32;
                        if (gk < H_)
                            av[rr] = __ldcg(reinterpret_cast<const float4*>(&g_h[m * H_ + gk]));
                        else
                            av[rr] = *reinterpret_cast<const float4*>(
                                &x[(size_t)m * (T_ * I_) + (size_t)t * I_ + (gk - H_)]);
                    }
                    const size_t base = (size_t)(nbase + b_n) * K_ + (kg + b_kq);
                    bv[0] = *reinterpret_cast<const uint4*>(&g_Whi[base]);
                    bv[1] = *reinterpret_cast<const uint4*>(&g_Whi[base + 8]);
                    bv[2] = *reinterpret_cast<const uint4*>(&g_Wlo[base]);
                    bv[3] = *reinterpret_cast<const uint4*>(&g_Wlo[base + 8]);
                }

                {
                    const __nv_bfloat16* sA_hi = smem + (s & 1) * HM_PER_BUF;
                    const __nv_bfloat16* sA_lo = sA_hi + 5120;
                    const __nv_bfloat16* sB_hi = sA_hi + 10240;
                    const __nv_bfloat16* sB_lo = sA_hi + 15360;
                    #pragma unroll
                    for (int k2 = 0; k2 < 2; k2++) {
                        const int kk = k2 * 16 + tig * 2;
                        uint32_t ahi[2][4], alo[2][4];
                        #pragma unroll
                        for (int mt = 0; mt < 2; mt++) {
                            const int m = wm * 32 + mt * 16 + g;
                            ahi[mt][0] = *reinterpret_cast<const uint32_t*>(&sA_hi[m * LDSS + kk]);
                            ahi[mt][1] = *reinterpret_cast<const uint32_t*>(&sA_hi[(m + 8) * LDSS + kk]);
                            ahi[mt][2] = *reinterpret_cast<const uint32_t*>(&sA_hi[m * LDSS + kk + 8]);
                            ahi[mt][3] = *reinterpret_cast<const uint32_t*>(&sA_hi[(m + 8) * LDSS + kk + 8]);
                            alo[mt][0] = *reinterpret_cast<const uint32_t*>(&sA_lo[m * LDSS + kk]);
                            alo[mt][1] = *reinterpret_cast<const uint32_t*>(&sA_lo[(m + 8) * LDSS + kk]);
                            alo[mt][2] = *reinterpret_cast<const uint32_t*>(&sA_lo[m * LDSS + kk + 8]);
                            alo[mt][3] = *reinterpret_cast<const uint32_t*>(&sA_lo[(m + 8) * LDSS + kk + 8]);
                        }
                        #pragma unroll
                        for (int nt = 0; nt < 8; nt++) {
                            const int n = wn * 64 + nt * 8 + g;
                            const uint32_t bhi0 = *reinterpret_cast<const uint32_t*>(&sB_hi[n * LDSS + kk]);
                            const uint32_t bhi1 = *reinterpret_cast<const uint32_t*>(&sB_hi[n * LDSS + kk + 8]);
                            const uint32_t blo0 = *reinterpret_cast<const uint32_t*>(&sB_lo[n * LDSS + kk]);
                            const uint32_t blo1 = *reinterpret_cast<const uint32_t*>(&sB_lo[n * LDSS + kk + 8]);
                            #pragma unroll
                            for (int mt = 0; mt < 2; mt++) {
                                mma_bf16(c[mt][nt], ahi[mt], bhi0, bhi1);
                                mma_bf16(c[mt][nt], ahi[mt], blo0, blo1);
                                mma_bf16(c[mt][nt], alo[mt], bhi0, bhi1);
                            }
                        }
                    }
                }
                __syncthreads();
            }
        }

        #pragma unroll
        for (int mt = 0; mt < 2; mt++) {
            #pragma unroll
            for (int nt = 0; nt < 8; nt++) {
                const int m = wm * 32 + mt * 16 + g;
                const int n = nbase + wn * 64 + nt * 8 + tig * 2;
                float2 v0 = make_float2(c[mt][nt][0], c[mt][nt][1]);
                float2 v1 = make_float2(c[mt][nt][2], c[mt][nt][3]);
                *reinterpret_cast<float2*>(&g_P[(size_t)(ks * B_ + m) * H_ + n])     = v0;
                *reinterpret_cast<float2*>(&g_P[(size_t)(ks * B_ + m + 8) * H_ + n]) = v1;
            }
        }

        grid_barrier(bx, 2u * (unsigned)t + 1u);

        {
            const int m = bx;
            const int n = tid * 8;
            float4 s0 = *reinterpret_cast<const float4*>(&g_bias[n]);
            float4 s1 = *reinterpret_cast<const float4*>(&g_bias[n + 4]);
            #pragma unroll
            for (int p = 0; p < KSPLIT; p++) {
                const float4 v0 = __ldcg(reinterpret_cast<const float4*>(
                    &g_P[(size_t)(p * B_ + m) * H_ + n]));
                const float4 v1 = __ldcg(reinterpret_cast<const float4*>(
                    &g_P[(size_t)(p * B_ + m) * H_ + n + 4]));
                s0.x += v0.x; s0.y += v0.y; s0.z += v0.z; s0.w += v0.w;
                s1.x += v1.x; s1.y += v1.y; s1.z += v1.z; s1.w += v1.w;
            }
            float4 h0v, h1v;
            h0v.x = tanhf(s0.x); h0v.y = tanhf(s0.y); h0v.z = tanhf(s0.z); h0v.w = tanhf(s0.w);
            h1v.x = tanhf(s1.x); h1v.y = tanhf(s1.y); h1v.z = tanhf(s1.z); h1v.w = tanhf(s1.w);
            *reinterpret_cast<float4*>(&g_h[m * H_ + n])     = h0v;
            *reinterpret_cast<float4*>(&g_h[m * H_ + n + 4]) = h1v;
            if (g_pad[m] == t) {
                *reinterpret_cast<float4*>(&g_hsave[m * H_ + n])     = h0v;
                *reinterpret_cast<float4*>(&g_hsave[m * H_ + n + 4]) = h1v;
            }
        }

        grid_barrier(bx, 2u * (unsigned)t + 2u);
    }
#endif
}

// ---------------------------------------------------------------------------
// Final FC: out[b][o] = b_fc[o] + hsave[b] . W_fc[o]
// ---------------------------------------------------------------------------
__global__ void __launch_bounds__(128)
fc_kernel(const float* __restrict__ Wfc, const float* __restrict__ bfc,
          float* __restrict__ out) {
    __shared__ float hs[2 * H_];
    const int bb  = blockIdx.x >> 2;
    const int oq  = blockIdx.x & 3;
    const int tid = threadIdx.x;

    const float* src = &g_hsave[(size_t)(bb * 2) * H_];
    for (int i = tid * 4; i < 2 * H_; i += 128 * 4)
        *reinterpret_cast<float4*>(&hs[i]) =
            *reinterpret_cast<const float4*>(&src[i]);
    __syncthreads();

    const int o = oq * 128 + tid;
    const float* w = &Wfc[(size_t)o * H_];
    float a0 = 0.0f, a1 = 0.0f;
    for (int n = 0; n < H_; n += 4) {
        const float4 wv  = *reinterpret_cast<const float4*>(&w[n]);
        const float4 h0v = *reinterpret_cast<const float4*>(&hs[n]);
        const float4 h1v = *reinterpret_cast<const float4*>(&hs[H_ + n]);
        a0 += wv.x * h0v.x + wv.y * h0v.y + wv.z * h0v.z + wv.w * h0v.w;
        a1 += wv.x * h1v.x + wv.y * h1v.y + wv.z * h1v.z + wv.w * h1v.w;
    }
    const float bias = bfc[o];
    out[(size_t)(bb * 2 + 0) * O_ + o] = a0 + bias;
    out[(size_t)(bb * 2 + 1) * O_ + o] = a1 + bias;
}

// ---------------------------------------------------------------------------
extern "C" void kernel_launch(void* const* d_in, const int* in_sizes, int n_in,
                              void* d_out, int out_size) {
    (void)in_sizes; (void)n_in; (void)out_size;
    const float* x   = (const float*)d_in[0];
    const float* h0  = (const float*)d_in[1];
    const float* Wih = (const float*)d_in[2];
    const float* bih = (const float*)d_in[3];
    const float* Whh = (const float*)d_in[4];
    const float* bhh = (const float*)d_in[5];
    const float* Wfc = (const float*)d_in[6];
    const float* bfc = (const float*)d_in[7];
    float* out = (float*)d_out;

    // idempotent, capture-safe, no static guards
    cudaFuncSetAttribute(rnn_persistent,
                         cudaFuncAttributeMaxDynamicSharedMemorySize, SMEM_TOTAL);

    setup_kernel<<<2048, 256>>>(x, h0, Wih, bih, Whh, bhh);
    rnn_persistent<<<NCTA, 256, SMEM_TOTAL>>>(x);
    fc_kernel<<<256, 128>>>(Wfc, bfc, out);
}

// round 17
// speedup vs baseline: 1.1817x; 1.0034x over previous
#include <cuda_runtime.h>
#include <cuda_bf16.h>
#include <cstdint>

// Problem constants
#define B_    128
#define T_    512
#define I_    512
#define H_    2048
#define O_    512
#define STEPS 510
#define K_    (H_ + I_)        // 2560 concatenated K ([h | x_t] vs [W_hh | W_ih])
#define KSPLIT 8
#define KCHUNK 320             // K per CTA
#define NCTA   128

// ---- arch-feature gate: tcgen05 exists only on sm_103a-targeted passes ----
#if defined(__CUDA_ARCH__) && defined(__CUDA_ARCH_FEAT_SM103_ALL)
#define TC_PATH 1
#else
#define TC_PATH 0
#endif

// ---- tcgen05-path constants ----
#define KB_TC     64           // bf16 k per smem stage (one SW128 atom row)
#define NSTAGE_TC 5            // 320 / 64
#define SM_TMEM   0
#define SM_MBAR0  8
#define SM_MBAR1  16
// W resident in smem for the whole kernel (pre-swizzled 16KB blocks/stage):
#define SM_BRES_HI 1024                    // 5 x 16KB = 80KB
#define SM_BRES_LO (SM_BRES_HI + 81920)    // 5 x 16KB = 80KB -> 82944
#define SM_ABUF    (SM_BRES_LO + 81920)    // 164864; 2 bufs x (Ahi 16KB + Alo 16KB)
#define ABUF_BYTES 32768
#define MAT_BYTES  16384       // 128 rows x 128 bytes
// idesc kind::f16: f32 acc(1<<4), bf16 A(1<<7), bf16 B(1<<10), N=128(16<<17), M=128(8<<24)
#define IDESC 0x8200490u

// ---- HMMA-fallback constants ----
#define KB_HM     32
#define NSTAGE_HM 10           // 320 / 32
#define LDSS      40           // bf16 per smem row (conflict-free)
#define HM_PER_BUF 20480       // bf16 elems: Ahi Alo Bhi Blo (5120 each)

// dynamic smem: TC path needs 164864 + 65536 = 230400 (fallback uses 81920 of it)
#define SMEM_TOTAL 230400

// -------- device scratch (static allocation only) ---------------------------
// Layout of g_Whi/g_Wlo depends on compiled path (setup writes the matching one):
//   TC_PATH:  per-(ni,ks) 5 contiguous 16KB SW128 smem-image blocks
//   fallback: linear [n][k]
__device__ __nv_bfloat16 g_Whi[(size_t)H_ * K_];   // 10.5 MB
__device__ __nv_bfloat16 g_Wlo[(size_t)H_ * K_];   // 10.5 MB
__device__ float g_h[B_ * H_];
__device__ float g_hsave[B_ * H_];
__device__ float g_bias[H_];
__device__ int   g_pad[B_];
__device__ float g_P[KSPLIT * B_ * H_];            // fp32 K-split partials (8 MB)
__device__ unsigned g_arrive[NCTA];                // distributed barrier flags

// ---------------------------------------------------------------------------
// Setup: barrier reset, pad, h init, bias, W -> bf16 hi/lo split.
// ---------------------------------------------------------------------------
__global__ void setup_kernel(const float* __restrict__ x,
                             const float* __restrict__ h0,
                             const float* __restrict__ Wih,
                             const float* __restrict__ bih,
                             const float* __restrict__ Whh,
                             const float* __restrict__ bhh) {
    long long idx    = (long long)blockIdx.x * blockDim.x + threadIdx.x;
    long long stride = (long long)gridDim.x * blockDim.x;

    for (long long i = idx; i < NCTA; i += stride) g_arrive[i] = 0u;

    for (long long i = idx; i < (long long)H_ * K_; i += stride) {
        int n = (int)(i / K_);
        int k = (int)(i % K_);
        float w = (k < H_) ? Whh[(size_t)n * H_ + k] : Wih[(size_t)n * I_ + (k - H_)];
        __nv_bfloat16 hi = __float2bfloat16(w);
        float lof = w - __bfloat162float(hi);
#if TC_PATH
        // swizzled block layout for SS-mode descriptors
        int ni = n >> 7, np = n & 127;
        int ks = k / KCHUNK, r = k % KCHUNK, s = r >> 6, kk = r & 63;
        size_t blk = (size_t)((ni * 8 + ks) * NSTAGE_TC + s);
        uint32_t off = (uint32_t)(np * 128 + kk * 2);
        uint32_t sw  = off ^ ((off >> 3) & 0x70);
        size_t di = blk * 8192 + (sw >> 1);
#else
        size_t di = (size_t)i;   // linear
#endif
        g_Whi[di] = hi;
        g_Wlo[di] = __float2bfloat16(lof);
    }
    for (long long i = idx; i < (long long)B_ * H_; i += stride)
        g_h[i] = h0[i % H_];
    for (long long i = idx; i < H_; i += stride)
        g_bias[i] = bih[i] + bhh[i];
    for (long long i = idx; i < B_; i += stride)
        g_pad[i] = (int)(x[i * (long long)(T_ * I_) + (long long)(T_ - 1) * I_] + 0.5f);
}

// ---------------------------------------------------------------------------
// helpers
// ---------------------------------------------------------------------------
__device__ __forceinline__ void split2(float a, float b, uint32_t& hi, uint32_t& lo) {
    __nv_bfloat162 h, l;
    h.x = __float2bfloat16(a); h.y = __float2bfloat16(b);
    l.x = __float2bfloat16(a - __bfloat162float(h.x));
    l.y = __float2bfloat16(b - __bfloat162float(h.y));
    hi = *reinterpret_cast<uint32_t*>(&h);
    lo = *reinterpret_cast<uint32_t*>(&l);
}

// Distributed grid barrier across the 128 co-resident CTAs.
__device__ __forceinline__ void grid_barrier(int bx, unsigned epoch) {
    __threadfence();
    __syncthreads();
    if (threadIdx.x == 0) {
        asm volatile("st.release.gpu.u32 [%0], %1;"
                     :: "l"(&g_arrive[bx]), "r"(epoch) : "memory");
    }
    if (threadIdx.x < NCTA) {
        unsigned v;
        do {
            asm volatile("ld.acquire.gpu.u32 %0, [%1];"
                         : "=r"(v) : "l"(&g_arrive[threadIdx.x]) : "memory");
        } while (v < epoch);
    }
    __syncthreads();
}

#if TC_PATH
__device__ __forceinline__ uint32_t elect_one() {
    uint32_t p;
    asm volatile("{\n\t.reg .pred p;\n\telect.sync _|p, 0xFFFFFFFF;\n\t"
                 "selp.b32 %0, 1, 0, p;\n\t}" : "=r"(p));
    return p;
}
__device__ __forceinline__ uint64_t sdesc(uint32_t addr) {
    // SW128 K-major: layout=2, version=1, SBO=64, LBO=1
    const uint64_t base = (2ULL << 61) | (1ULL << 46) | (64ULL << 32) | (1ULL << 16);
    return base | ((addr >> 4) & 0x3FFF);
}
__device__ __forceinline__ void mma_ss(uint32_t d, uint64_t ad, uint64_t bd,
                                       uint32_t idesc, uint32_t enable) {
    asm volatile(
        "{\n\t.reg .pred p;\n\tsetp.ne.u32 p, %4, 0;\n\t"
        "tcgen05.mma.cta_group::1.kind::f16 [%0], %1, %2, %3, {%5,%5,%5,%5}, p;\n\t}"
        :: "r"(d), "l"(ad), "l"(bd), "r"(idesc), "r"(enable), "r"(0u) : "memory");
}
__device__ __forceinline__ void mbar_wait(uint32_t addr, unsigned parity) {
    asm volatile(
        "{\n\t.reg .pred P1;\n\t"
        "WAIT_LOOP_%=:\n\t"
        "mbarrier.try_wait.parity.acquire.cta.shared::cta.b64 P1, [%0], %1, 0x989680;\n\t"
        "@P1 bra.uni WAIT_DONE_%=;\n\t"
        "bra.uni WAIT_LOOP_%=;\n\t"
        "WAIT_DONE_%=:\n\t}"
        :: "r"(addr), "r"(parity) : "memory");
}
#else
// bf16 MMA: D += A * B  (m16n8k16, fp32 accumulate) — fallback tensor path
__device__ __forceinline__ void mma_bf16(float c[4], const uint32_t a[4],
                                         uint32_t b0, uint32_t b1) {
    asm volatile(
        "mma.sync.aligned.m16n8k16.row.col.f32.bf16.bf16.f32 "
        "{%0,%1,%2,%3}, {%4,%5,%6,%7}, {%8,%9}, {%0,%1,%2,%3};"
        : "+f"(c[0]), "+f"(c[1]), "+f"(c[2]), "+f"(c[3])
        : "r"(a[0]), "r"(a[1]), "r"(a[2]), "r"(a[3]), "r"(b0), "r"(b1));
}
#endif

// ---------------------------------------------------------------------------
// Persistent RNN kernel: all 510 steps. 128 CTAs x 256 threads, 1 CTA/SM.
// CTA (ks=bx&7, ni=bx>>3): D[128 batch x 128 n] over K-chunk [ks*320,+320)
// with bf16x3 split products. TC path: W slice resident in SMEM all kernel,
// A double-buffered (fill s+1 overlaps MMA s, per-buffer mbarrier epochs).
// Then: fp32 partials -> grid barrier -> fused reduce+bias+tanh (CTA bx owns
// batch row bx) with pad snapshot -> grid barrier.
// ---------------------------------------------------------------------------
__global__ void __launch_bounds__(256, 1) __cluster_dims__(1, 1, 1)
rnn_persistent(const float* __restrict__ x) {
    extern __shared__ char smemc[];

    const int bx   = blockIdx.x;
    const int ks   = bx & 7;
    const int ni   = bx >> 3;
    const int tid  = threadIdx.x;
    const int wid  = tid >> 5;
    const int lane = tid & 31;
    const int k0    = ks * KCHUNK;
    const int nbase = ni * 128;

#if TC_PATH
    // ===================== tcgen05 mainloop (B-resident, A dbl-buffered) ===
    uint32_t smem_u32;
    asm("{ .reg .u64 t; cvta.to.shared.u64 t, %1; cvt.u32.u64 %0, t; }"
        : "=r"(smem_u32) : "l"(smemc));

    const int mrow = tid >> 1;     // A-fill: thread -> (row, 32-float half)
    const int half = tid & 1;
    const int mx   = mrow & 7;     // swizzle XOR for row's 16B chunks

    // TMEM alloc by warp 0 only
    if (wid == 0) {
        asm volatile("tcgen05.alloc.cta_group::1.sync.aligned.shared::cta.b32 [%0], %1;"
                     :: "r"(smem_u32 + SM_TMEM), "r"(512) : "memory");
    }
    if (tid == 0) {
        asm volatile("mbarrier.init.shared.b64 [%0], %1;"
                     :: "r"(smem_u32 + SM_MBAR0), "r"(1) : "memory");
        asm volatile("mbarrier.init.shared.b64 [%0], %1;"
                     :: "r"(smem_u32 + SM_MBAR1), "r"(1) : "memory");
    }
    __syncthreads();
    uint32_t tmem;
    asm volatile("ld.shared.b32 %0, [%1];" : "=r"(tmem) : "r"(smem_u32 + SM_TMEM));

    // ---- one-time: copy this CTA's W slice (pre-swizzled) into resident smem
    {
        const size_t blk0 = (size_t)(ni * 8 + ks) * NSTAGE_TC;  // 5 contiguous blocks
        const uint4* srcH = reinterpret_cast<const uint4*>(g_Whi) + blk0 * 1024;
        const uint4* srcL = reinterpret_cast<const uint4*>(g_Wlo) + blk0 * 1024;
        uint4* dH = reinterpret_cast<uint4*>(smemc + SM_BRES_HI);
        uint4* dL = reinterpret_cast<uint4*>(smemc + SM_BRES_LO);
        #pragma unroll
        for (int i = 0; i < 20; i++) {          // 5120 uint4 / 256 threads
            dH[i * 256 + tid] = srcH[i * 256 + tid];
            dL[i * 256 + tid] = srcL[i * 256 + tid];
        }
        asm volatile("fence.proxy.async.shared::cta;" ::: "memory");
        __syncthreads();
    }

    unsigned uses[2] = {0u, 0u};   // commits issued per A buffer

    for (int t = 0; t < STEPS; t++) {
        for (int s = 0; s < NSTAGE_TC; s++) {
            const int b = s & 1;
            const uint32_t mb = smem_u32 + (b ? SM_MBAR1 : SM_MBAR0);
            if (uses[b] > 0) mbar_wait(mb, (uses[b] - 1) & 1);  // buffer reusable

            char* abuf = smemc + SM_ABUF + b * ABUF_BYTES;
            const int kg = k0 + s * KB_TC;

            // ---- A fill: 128 x 64 fp32 -> bf16 hi/lo, SW128-swizzled ----
            {
                const float* srcA = (kg < H_)
                    ? &g_h[mrow * H_ + kg + half * 32]
                    : &x[(size_t)mrow * (T_ * I_) + (size_t)t * I_ + (kg - H_) + half * 32];
                char* bh = abuf + mrow * 128;
                char* bl = bh + MAT_BYTES;
                #pragma unroll
                for (int i2 = 0; i2 < 4; i2++) {
                    float4 f0 = __ldcg(reinterpret_cast<const float4*>(srcA + i2 * 8));
                    float4 f1 = __ldcg(reinterpret_cast<const float4*>(srcA + i2 * 8 + 4));
                    uint4 hv, lv;
                    split2(f0.x, f0.y, hv.x, lv.x);
                    split2(f0.z, f0.w, hv.y, lv.y);
                    split2(f1.x, f1.y, hv.z, lv.z);
                    split2(f1.z, f1.w, hv.w, lv.w);
                    const int q = ((half * 4 + i2) ^ mx) * 16;
                    *reinterpret_cast<uint4*>(bh + q) = hv;
                    *reinterpret_cast<uint4*>(bl + q) = lv;
                }
            }
            asm volatile("fence.proxy.async.shared::cta;" ::: "memory");
            __syncthreads();

            // ---- MMA issue (overlaps next stage's fill): 4 k16 x 3 products
            if (wid == 0) {
                asm volatile("tcgen05.fence::after_thread_sync;" ::: "memory");
                if (elect_one()) {
                    const uint32_t aaddr = smem_u32 + SM_ABUF + b * ABUF_BYTES;
                    const uint64_t dAh = sdesc(aaddr);
                    const uint64_t dAl = sdesc(aaddr + MAT_BYTES);
                    const uint64_t dBh = sdesc(smem_u32 + SM_BRES_HI + s * MAT_BYTES);
                    const uint64_t dBl = sdesc(smem_u32 + SM_BRES_LO + s * MAT_BYTES);
                    #pragma unroll
                    for (int j = 0; j < 4; j++) {
                        const unsigned en0 = (s == 0 && j == 0) ? 0u : 1u;
                        mma_ss(tmem, dAh + 2 * j, dBh + 2 * j, IDESC, en0);  // hi*hi
                        mma_ss(tmem, dAh + 2 * j, dBl + 2 * j, IDESC, 1u);  // hi*lo
                        mma_ss(tmem, dAl + 2 * j, dBh + 2 * j, IDESC, 1u);  // lo*hi
                    }
                    asm volatile(
                        "tcgen05.commit.cta_group::1.mbarrier::arrive::one.shared::cluster.b64 [%0];"
                        :: "r"(mb) : "memory");
                }
            }
            uses[b]++;
        }

        // ---- wait for all step MMAs (both buffers' last commits) ----
        if (uses[1] > 0) mbar_wait(smem_u32 + SM_MBAR1, (uses[1] - 1) & 1);
        mbar_wait(smem_u32 + SM_MBAR0, (uses[0] - 1) & 1);
        asm volatile("tcgen05.fence::after_thread_sync;" ::: "memory");

        // ---- epilogue: warps 0-3 read D from TMEM, write fp32 partials ----
        if (wid < 4) {
            const int mr = wid * 32 + lane;
            float* dst = &g_P[(size_t)(ks * B_ + mr) * H_ + nbase];
            #pragma unroll
            for (int cb = 0; cb < 4; cb++) {
                uint32_t r[32];
                asm volatile(
                    "tcgen05.ld.sync.aligned.32x32b.x32.b32 "
                    "{%0, %1, %2, %3, %4, %5, %6, %7, "
                    " %8, %9, %10, %11, %12, %13, %14, %15, "
                    " %16, %17, %18, %19, %20, %21, %22, %23, "
                    " %24, %25, %26, %27, %28, %29, %30, %31}, [%32];"
                    : "=r"(r[0]), "=r"(r[1]), "=r"(r[2]), "=r"(r[3]),
                      "=r"(r[4]), "=r"(r[5]), "=r"(r[6]), "=r"(r[7]),
                      "=r"(r[8]), "=r"(r[9]), "=r"(r[10]), "=r"(r[11]),
                      "=r"(r[12]), "=r"(r[13]), "=r"(r[14]), "=r"(r[15]),
                      "=r"(r[16]), "=r"(r[17]), "=r"(r[18]), "=r"(r[19]),
                      "=r"(r[20]), "=r"(r[21]), "=r"(r[22]), "=r"(r[23]),
                      "=r"(r[24]), "=r"(r[25]), "=r"(r[26]), "=r"(r[27]),
                      "=r"(r[28]), "=r"(r[29]), "=r"(r[30]), "=r"(r[31])
                    : "r"(tmem + cb * 32));
                asm volatile("tcgen05.wait::ld.sync.aligned;" ::: "memory");
                #pragma unroll
                for (int i2 = 0; i2 < 8; i2++) {
                    float4 v = make_float4(__uint_as_float(r[i2 * 4 + 0]),
                                           __uint_as_float(r[i2 * 4 + 1]),
                                           __uint_as_float(r[i2 * 4 + 2]),
                                           __uint_as_float(r[i2 * 4 + 3]));
                    *reinterpret_cast<float4*>(dst + cb * 32 + i2 * 4) = v;
                }
            }
            asm volatile("tcgen05.fence::before_thread_sync;" ::: "memory");
        }

        grid_barrier(bx, 2u * (unsigned)t + 1u);

        // ---- reduce + bias + tanh; CTA bx owns batch row bx ----
        {
            const int m = bx;
            const int n = tid * 8;
            float4 s0 = *reinterpret_cast<const float4*>(&g_bias[n]);
            float4 s1 = *reinterpret_cast<const float4*>(&g_bias[n + 4]);
            #pragma unroll
            for (int p = 0; p < KSPLIT; p++) {
                const float4 v0 = __ldcg(reinterpret_cast<const float4*>(
                    &g_P[(size_t)(p * B_ + m) * H_ + n]));
                const float4 v1 = __ldcg(reinterpret_cast<const float4*>(
                    &g_P[(size_t)(p * B_ + m) * H_ + n + 4]));
                s0.x += v0.x; s0.y += v0.y; s0.z += v0.z; s0.w += v0.w;
                s1.x += v1.x; s1.y += v1.y; s1.z += v1.z; s1.w += v1.w;
            }
            float4 h0v, h1v;
            h0v.x = tanhf(s0.x); h0v.y = tanhf(s0.y); h0v.z = tanhf(s0.z); h0v.w = tanhf(s0.w);
            h1v.x = tanhf(s1.x); h1v.y = tanhf(s1.y); h1v.z = tanhf(s1.z); h1v.w = tanhf(s1.w);
            *reinterpret_cast<float4*>(&g_h[m * H_ + n])     = h0v;
            *reinterpret_cast<float4*>(&g_h[m * H_ + n + 4]) = h1v;
            if (g_pad[m] == t) {
                *reinterpret_cast<float4*>(&g_hsave[m * H_ + n])     = h0v;
                *reinterpret_cast<float4*>(&g_hsave[m * H_ + n + 4]) = h1v;
            }
        }

        grid_barrier(bx, 2u * (unsigned)t + 2u);
    }

    __syncthreads();
    if (tid == 0) {
        asm volatile("mbarrier.inval.shared.b64 [%0];" :: "r"(smem_u32 + SM_MBAR0) : "memory");
        asm volatile("mbarrier.inval.shared.b64 [%0];" :: "r"(smem_u32 + SM_MBAR1) : "memory");
    }
    __syncthreads();
    if (wid == 0) {
        asm volatile("tcgen05.dealloc.cta_group::1.sync.aligned.b32 %0, %1;"
                     :: "r"(tmem), "r"(512));
    }

#else
    // ===================== HMMA fallback (R11-proven) ======================
    __nv_bfloat16* smem = reinterpret_cast<__nv_bfloat16*>(smemc);

    const int wm  = wid & 3;
    const int wn  = wid >> 2;
    const int g   = lane >> 2;
    const int tig = lane & 3;

    const int a_row = tid >> 3;
    const int a_kq  = (tid & 7) * 4;
    const int b_n   = tid >> 1;
    const int b_kq  = (tid & 1) * 16;

    float c[2][8][4];
    float4 av[4];
    uint4  bv[4];

    for (int t = 0; t < STEPS; t++) {
        #pragma unroll
        for (int mt = 0; mt < 2; mt++)
            #pragma unroll
            for (int nt = 0; nt < 8; nt++)
                #pragma unroll
                for (int j = 0; j < 4; j++) c[mt][nt][j] = 0.0f;

        {
            {
                const int kg = k0;
                const int gk = kg + a_kq;
                #pragma unroll
                for (int rr = 0; rr < 4; rr++) {
                    const int m = a_row + rr * 32;
                    if (gk < H_)
                        av[rr] = __ldcg(reinterpret_cast<const float4*>(&g_h[m * H_ + gk]));
                    else
                        av[rr] = *reinterpret_cast<const float4*>(
                            &x[(size_t)m * (T_ * I_) + (size_t)t * I_ + (gk - H_)]);
                }
                const size_t base = (size_t)(nbase + b_n) * K_ + (kg + b_kq);
                bv[0] = *reinterpret_cast<const uint4*>(&g_Whi[base]);
                bv[1] = *reinterpret_cast<const uint4*>(&g_Whi[base + 8]);
                bv[2] = *reinterpret_cast<const uint4*>(&g_Wlo[base]);
                bv[3] = *reinterpret_cast<const uint4*>(&g_Wlo[base + 8]);
            }

            #pragma unroll 2
            for (int s = 0; s < NSTAGE_HM; s++) {
                {
                    __nv_bfloat16* sA_hi = smem + (s & 1) * HM_PER_BUF;
                    __nv_bfloat16* sA_lo = sA_hi + 5120;
                    __nv_bfloat16* sB_hi = sA_hi + 10240;
                    __nv_bfloat16* sB_lo = sA_hi + 15360;
                    #pragma unroll
                    for (int rr = 0; rr < 4; rr++) {
                        const int m = a_row + rr * 32;
                        float vv[4] = {av[rr].x, av[rr].y, av[rr].z, av[rr].w};
                        #pragma unroll
                        for (int j = 0; j < 4; j += 2) {
                            uint32_t hp, lp;
                            split2(vv[j], vv[j + 1], hp, lp);
                            *reinterpret_cast<uint32_t*>(&sA_hi[m * LDSS + a_kq + j]) = hp;
                            *reinterpret_cast<uint32_t*>(&sA_lo[m * LDSS + a_kq + j]) = lp;
                        }
                    }
                    *reinterpret_cast<uint4*>(&sB_hi[b_n * LDSS + b_kq])     = bv[0];
                    *reinterpret_cast<uint4*>(&sB_hi[b_n * LDSS + b_kq + 8]) = bv[1];
                    *reinterpret_cast<uint4*>(&sB_lo[b_n * LDSS + b_kq])     = bv[2];
                    *reinterpret_cast<uint4*>(&sB_lo[b_n * LDSS + b_kq + 8]) = bv[3];
                }
                __syncthreads();

                if (s + 1 < NSTAGE_HM) {
                    const int kg = k0 + (s + 1) * KB_HM;
                    const int gk = kg + a_kq;
                    #pragma unroll
                    for (int rr = 0; rr < 4; rr++) {
                        const int m = a_row + rr * 32;
                        if (gk < H_)
                            av[rr] = __ldcg(reinterpret_cast<const float4*>(&g_h[m * H_ + gk]));
                        else
                            av[rr] = *reinterpret_cast<const float4*>(
                                &x[(size_t)m * (T_ * I_) + (size_t)t * I_ + (gk - H_)]);
                    }
                    const size_t base = (size_t)(nbase + b_n) * K_ + (kg + b_kq);
                    bv[0] = *reinterpret_cast<const uint4*>(&g_Whi[base]);
                    bv[1] = *reinterpret_cast<const uint4*>(&g_Whi[base + 8]);
                    bv[2] = *reinterpret_cast<const uint4*>(&g_Wlo[base]);
                    bv[3] = *reinterpret_cast<const uint4*>(&g_Wlo[base + 8]);
                }

                {
                    const __nv_bfloat16* sA_hi = smem + (s & 1) * HM_PER_BUF;
                    const __nv_bfloat16* sA_lo = sA_hi + 5120;
                    const __nv_bfloat16* sB_hi = sA_hi + 10240;
                    const __nv_bfloat16* sB_lo = sA_hi + 15360;
                    #pragma unroll
                    for (int k2 = 0; k2 < 2; k2++) {
                        const int kk = k2 * 16 + tig * 2;
                        uint32_t ahi[2][4], alo[2][4];
                        #pragma unroll
                        for (int mt = 0; mt < 2; mt++) {
                            const int m = wm * 32 + mt * 16 + g;
                            ahi[mt][0] = *reinterpret_cast<const uint32_t*>(&sA_hi[m * LDSS + kk]);
                            ahi[mt][1] = *reinterpret_cast<const uint32_t*>(&sA_hi[(m + 8) * LDSS + kk]);
                            ahi[mt][2] = *reinterpret_cast<const uint32_t*>(&sA_hi[m * LDSS + kk + 8]);
                            ahi[mt][3] = *reinterpret_cast<const uint32_t*>(&sA_hi[(m + 8) * LDSS + kk + 8]);
                            alo[mt][0] = *reinterpret_cast<const uint32_t*>(&sA_lo[m * LDSS + kk]);
                            alo[mt][1] = *reinterpret_cast<const uint32_t*>(&sA_lo[(m + 8) * LDSS + kk]);
                            alo[mt][2] = *reinterpret_cast<const uint32_t*>(&sA_lo[m * LDSS + kk + 8]);
                            alo[mt][3] = *reinterpret_cast<const uint32_t*>(&sA_lo[(m + 8) * LDSS + kk + 8]);
                        }
                        #pragma unroll
                        for (int nt = 0; nt < 8; nt++) {
                            const int n = wn * 64 + nt * 8 + g;
                            const uint32_t bhi0 = *reinterpret_cast<const uint32_t*>(&sB_hi[n * LDSS + kk]);
                            const uint32_t bhi1 = *reinterpret_cast<const uint32_t*>(&sB_hi[n * LDSS + kk + 8]);
                            const uint32_t blo0 = *reinterpret_cast<const uint32_t*>(&sB_lo[n * LDSS + kk]);
                            const uint32_t blo1 = *reinterpret_cast<const uint32_t*>(&sB_lo[n * LDSS + kk + 8]);
                            #pragma unroll
                            for (int mt = 0; mt < 2; mt++) {
                                mma_bf16(c[mt][nt], ahi[mt], bhi0, bhi1);
                                mma_bf16(c[mt][nt], ahi[mt], blo0, blo1);
                                mma_bf16(c[mt][nt], alo[mt], bhi0, bhi1);
                            }
                        }
                    }
                }
                __syncthreads();
            }
        }

        #pragma unroll
        for (int mt = 0; mt < 2; mt++) {
            #pragma unroll
            for (int nt = 0; nt < 8; nt++) {
                const int m = wm * 32 + mt * 16 + g;
                const int n = nbase + wn * 64 + nt * 8 + tig * 2;
                float2 v0 = make_float2(c[mt][nt][0], c[mt][nt][1]);
                float2 v1 = make_float2(c[mt][nt][2], c[mt][nt][3]);
                *reinterpret_cast<float2*>(&g_P[(size_t)(ks * B_ + m) * H_ + n])     = v0;
                *reinterpret_cast<float2*>(&g_P[(size_t)(ks * B_ + m + 8) * H_ + n]) = v1;
            }
        }

        grid_barrier(bx, 2u * (unsigned)t + 1u);

        {
            const int m = bx;
            const int n = tid * 8;
            float4 s0 = *reinterpret_cast<const float4*>(&g_bias[n]);
            float4 s1 = *reinterpret_cast<const float4*>(&g_bias[n + 4]);
            #pragma unroll
            for (int p = 0; p < KSPLIT; p++) {
                const float4 v0 = __ldcg(reinterpret_cast<const float4*>(
                    &g_P[(size_t)(p * B_ + m) * H_ + n]));
                const float4 v1 = __ldcg(reinterpret_cast<const float4*>(
                    &g_P[(size_t)(p * B_ + m) * H_ + n + 4]));
                s0.x += v0.x; s0.y += v0.y; s0.z += v0.z; s0.w += v0.w;
                s1.x += v1.x; s1.y += v1.y; s1.z += v1.z; s1.w += v1.w;
            }
            float4 h0v, h1v;
            h0v.x = tanhf(s0.x); h0v.y = tanhf(s0.y); h0v.z = tanhf(s0.z); h0v.w = tanhf(s0.w);
            h1v.x = tanhf(s1.x); h1v.y = tanhf(s1.y); h1v.z = tanhf(s1.z); h1v.w = tanhf(s1.w);
            *reinterpret_cast<float4*>(&g_h[m * H_ + n])     = h0v;
            *reinterpret_cast<float4*>(&g_h[m * H_ + n + 4]) = h1v;
            if (g_pad[m] == t) {
                *reinterpret_cast<float4*>(&g_hsave[m * H_ + n])     = h0v;
                *reinterpret_cast<float4*>(&g_hsave[m * H_ + n + 4]) = h1v;
            }
        }

        grid_barrier(bx, 2u * (unsigned)t + 2u);
    }
#endif
}

// ---------------------------------------------------------------------------
// Final FC: out[b][o] = b_fc[o] + hsave[b] . W_fc[o]
// ---------------------------------------------------------------------------
__global__ void __launch_bounds__(128)
fc_kernel(const float* __restrict__ Wfc, const float* __restrict__ bfc,
          float* __restrict__ out) {
    __shared__ float hs[2 * H_];
    const int bb  = blockIdx.x >> 2;
    const int oq  = blockIdx.x & 3;
    const int tid = threadIdx.x;

    const float* src = &g_hsave[(size_t)(bb * 2) * H_];
    for (int i = tid * 4; i < 2 * H_; i += 128 * 4)
        *reinterpret_cast<float4*>(&hs[i]) =
            *reinterpret_cast<const float4*>(&src[i]);
    __syncthreads();

    const int o = oq * 128 + tid;
    const float* w = &Wfc[(size_t)o * H_];
    float a0 = 0.0f, a1 = 0.0f;
    for (int n = 0; n < H_; n += 4) {
        const float4 wv  = *reinterpret_cast<const float4*>(&w[n]);
        const float4 h0v = *reinterpret_cast<const float4*>(&hs[n]);
        const float4 h1v = *reinterpret_cast<const float4*>(&hs[H_ + n]);
        a0 += wv.x * h0v.x + wv.y * h0v.y + wv.z * h0v.z + wv.w * h0v.w;
        a1 += wv.x * h1v.x + wv.y * h1v.y + wv.z * h1v.z + wv.w * h1v.w;
    }
    const float bias = bfc[o];
    out[(size_t)(bb * 2 + 0) * O_ + o] = a0 + bias;
    out[(size_t)(bb * 2 + 1) * O_ + o] = a1 + bias;
}

// ---------------------------------------------------------------------------
extern "C" void kernel_launch(void* const* d_in, const int* in_sizes, int n_in,
                              void* d_out, int out_size) {
    (void)in_sizes; (void)n_in; (void)out_size;
    const float* x   = (const float*)d_in[0];
    const float* h0  = (const float*)d_in[1];
    const float* Wih = (const float*)d_in[2];
    const float* bih = (const float*)d_in[3];
    const float* Whh = (const float*)d_in[4];
    const float* bhh = (const float*)d_in[5];
    const float* Wfc = (const float*)d_in[6];
    const float* bfc = (const float*)d_in[7];
    float* out = (float*)d_out;

    // idempotent, capture-safe, no static guards
    cudaFuncSetAttribute(rnn_persistent,
                         cudaFuncAttributeMaxDynamicSharedMemorySize, SMEM_TOTAL);

    setup_kernel<<<2048, 256>>>(x, h0, Wih, bih, Whh, bhh);
    rnn_persistent<<<NCTA, 256, SMEM_TOTAL>>>(x);
    fc_kernel<<<256, 128>>>(Wfc, bfc, out);
}